// round 1
// baseline (speedup 1.0000x reference)
#include <cuda_runtime.h>
#include <cstdint>
#include <cstddef>

// ============================================================================
// RiemannLinearTransform: out = x @ (irfft(U)·S @ irfft(V)).T + bias
// Restructured as 4 dense GEMMs against fixed trig basis matrices.
// All GEMMs: C[M,N] = A[M,K] @ B[N,K]^T  (NT form, fp32, packed f32x2 FMA)
// ============================================================================

static constexpr double PI_D = 3.141592653589793238462643383279502884;

// ---------------- scratch (device global, no allocations) ------------------
constexpr size_t SZ_B1 = 2048ull * 4096;   // Vh basis (rows: 1024 cos + 1024 sin) x 4096 cols
constexpr size_t SZ_G  = 1024ull * 2048;   // U  basis (rows: 512 cos + 512 sin)  x 2048 cols
constexpr size_t SZ_Y  = 1024ull * 2048;
constexpr size_t SZ_T  = 1024ull * 2048;
constexpr size_t SZ_Z  = 1024ull * 1024;

constexpr size_t OFF_B1      = 0;
constexpr size_t OFF_G       = OFF_B1 + SZ_B1;
constexpr size_t OFF_Y       = OFF_G + SZ_G;
constexpr size_t OFF_T       = OFF_Y + SZ_Y;
constexpr size_t OFF_Z       = OFF_T + SZ_T;
constexpr size_t OFF_TAB4096 = OFF_Z + SZ_Z;          // 4096 float2
constexpr size_t OFF_TAB2048 = OFF_TAB4096 + 8192;    // 2048 float2
constexpr size_t SCRATCH_FLOATS = OFF_TAB2048 + 4096;

__device__ __align__(16) float g_scratch[SCRATCH_FLOATS];

// ---------------- table generation ------------------------------------------
__global__ void gen_tables_kernel(float2* __restrict__ tab4096,
                                  float2* __restrict__ tab2048) {
    int t = blockIdx.x * blockDim.x + threadIdx.x;
    if (t < 4096) {
        double a = (2.0 * PI_D / 4096.0) * (double)t;
        tab4096[t] = make_float2((float)cos(a), (float)sin(a));
    }
    if (t < 2048) {
        double a = (2.0 * PI_D / 2048.0) * (double)t;
        tab2048[t] = make_float2((float)cos(a), (float)sin(a));
    }
}

// Basis matrix: rows [0,ncoef)  : k-th row = (k==0 ? 1/n : (2/n)cos(2*pi*j*k/n))
//               rows [ncoef,2n) : k-th row = (k==0 ? 0   : -(2/n)sin(2*pi*j*k/n))
// Matrix has n columns, 2*ncoef rows, row-major.
__global__ void fill_basis_kernel(float* __restrict__ out,
                                  const float2* __restrict__ tab,
                                  int n, int ncoef) {
    int j4 = blockIdx.x * blockDim.x + threadIdx.x;   // float4 index within row
    int kp = blockIdx.y;                              // row
    int ncols4 = n >> 2;
    if (j4 >= ncols4) return;
    bool is_sin = (kp >= ncoef);
    int k = is_sin ? (kp - ncoef) : kp;
    float inv = 1.0f / (float)n;
    int mask = n - 1;
    int jb = j4 << 2;
    float4 v;
    float* vv = &v.x;
#pragma unroll
    for (int e = 0; e < 4; e++) {
        if (k == 0) {
            vv[e] = is_sin ? 0.0f : inv;
        } else {
            int idx = ((jb + e) * k) & mask;
            float2 cs = tab[idx];
            vv[e] = is_sin ? (-2.0f * inv * cs.y) : (2.0f * inv * cs.x);
        }
    }
    *reinterpret_cast<float4*>(out + (size_t)kp * n + jb) = v;
}

// ---------------- packed f32x2 helpers ---------------------------------------
__device__ __forceinline__ unsigned long long pack_dup(float x) {
    unsigned long long r;
    asm("mov.b64 %0, {%1, %1};" : "=l"(r) : "f"(x));
    return r;
}
__device__ __forceinline__ void fma_f32x2(unsigned long long& acc,
                                          unsigned long long a,
                                          unsigned long long b) {
    asm("fma.rn.f32x2 %0, %1, %2, %0;" : "+l"(acc) : "l"(a), "l"(b));
}
__device__ __forceinline__ void unpack_f32x2(unsigned long long v, float& lo, float& hi) {
    asm("mov.b64 {%0, %1}, %2;" : "=f"(lo), "=f"(hi) : "l"(v));
}

// ---------------- generic NT GEMM --------------------------------------------
// C[M,N] = A[M,K] @ B^T, where logical B[n][k] = (k < Ksplit) ? B0[n*ldb + k]
//                                               : B1p[n*ldb + (k - Ksplit)]
// Optional per-column scale and bias. M % BM == 0, N % BN == 0, K % BK == 0,
// Ksplit % BK == 0 guaranteed by caller.
template <int BM, int BN, int BK, int TM, int TN>
__global__ void __launch_bounds__((BM / TM) * (BN / TN))
gemm_nt_kernel(const float* __restrict__ A, int lda,
               const float* __restrict__ B0, const float* __restrict__ B1p,
               int Ksplit, int ldb,
               float* __restrict__ C, int ldc,
               int K,
               const float* __restrict__ scale,
               const float* __restrict__ biasp) {
    constexpr int NT = (BM / TM) * (BN / TN);
    constexpr int CPR = BK / 4;  // float4 per K-row of a tile

    __shared__ __align__(16) float As[BK][BM];
    __shared__ __align__(16) float Bs[BK][BN];

    const int tid = threadIdx.x;
    const int tx = tid % (BN / TN);
    const int ty = tid / (BN / TN);
    const int i0 = blockIdx.y * BM;
    const int j0 = blockIdx.x * BN;

    unsigned long long acc[TM][TN / 2];
#pragma unroll
    for (int a = 0; a < TM; a++)
#pragma unroll
        for (int b = 0; b < TN / 2; b++) acc[a][b] = 0ull;

    for (int k0 = 0; k0 < K; k0 += BK) {
        // ---- load A tile (BM x BK), store transposed As[k][m] ----
        constexpr int A4 = BM * BK / 4;
#pragma unroll
        for (int s = tid; s < A4; s += NT) {
            int r = s / CPR;
            int c = s % CPR;
            float4 v = *reinterpret_cast<const float4*>(
                A + (size_t)(i0 + r) * lda + k0 + c * 4);
            As[c * 4 + 0][r] = v.x;
            As[c * 4 + 1][r] = v.y;
            As[c * 4 + 2][r] = v.z;
            As[c * 4 + 3][r] = v.w;
        }
        // ---- load B tile (BN x BK), store transposed Bs[k][n] ----
        const float* Bsrc;
        int kb;
        if (k0 < Ksplit) { Bsrc = B0; kb = k0; }
        else             { Bsrc = B1p; kb = k0 - Ksplit; }
        constexpr int B4 = BN * BK / 4;
#pragma unroll
        for (int s = tid; s < B4; s += NT) {
            int r = s / CPR;
            int c = s % CPR;
            float4 v = *reinterpret_cast<const float4*>(
                Bsrc + (size_t)(j0 + r) * ldb + kb + c * 4);
            Bs[c * 4 + 0][r] = v.x;
            Bs[c * 4 + 1][r] = v.y;
            Bs[c * 4 + 2][r] = v.z;
            Bs[c * 4 + 3][r] = v.w;
        }
        __syncthreads();

#pragma unroll
        for (int kk = 0; kk < BK; kk++) {
            float areg[TM];
#pragma unroll
            for (int q = 0; q < TM / 4; q++)
                *reinterpret_cast<float4*>(&areg[q * 4]) =
                    *reinterpret_cast<const float4*>(&As[kk][ty * TM + q * 4]);

            unsigned long long bp[TN / 2];
#pragma unroll
            for (int q = 0; q < TN / 4; q++) {
                ulonglong2 t = *reinterpret_cast<const ulonglong2*>(
                    &Bs[kk][tx * TN + q * 4]);
                bp[q * 2 + 0] = t.x;
                bp[q * 2 + 1] = t.y;
            }
#pragma unroll
            for (int im = 0; im < TM; im++) {
                unsigned long long ap = pack_dup(areg[im]);
#pragma unroll
                for (int q = 0; q < TN / 2; q++) fma_f32x2(acc[im][q], ap, bp[q]);
            }
        }
        __syncthreads();
    }

    // ---- epilogue ----
    const int colbase = j0 + tx * TN;
    float smul[TN];
    float badd[TN];
#pragma unroll
    for (int q = 0; q < TN; q++) {
        smul[q] = scale ? scale[colbase + q] : 1.0f;
        badd[q] = biasp ? biasp[colbase + q] : 0.0f;
    }
#pragma unroll
    for (int im = 0; im < TM; im++) {
        int row = i0 + ty * TM + im;
        float vals[TN];
#pragma unroll
        for (int q = 0; q < TN / 2; q++) {
            float lo, hi;
            unpack_f32x2(acc[im][q], lo, hi);
            vals[2 * q + 0] = lo;
            vals[2 * q + 1] = hi;
        }
#pragma unroll
        for (int q = 0; q < TN; q++) vals[q] = vals[q] * smul[q] + badd[q];
        float* crow = C + (size_t)row * ldc + colbase;
#pragma unroll
        for (int q = 0; q < TN / 4; q++)
            *reinterpret_cast<float4*>(crow + q * 4) =
                *reinterpret_cast<const float4*>(&vals[q * 4]);
    }
}

// ---------------- launcher ----------------------------------------------------
extern "C" void kernel_launch(void* const* d_in, const int* in_sizes, int n_in,
                              void* d_out, int out_size) {
    const float* x       = (const float*)d_in[0];   // (1024, 4096)
    const float* U_real  = (const float*)d_in[1];   // (4096, 512)
    const float* U_imag  = (const float*)d_in[2];   // (4096, 512)
    const float* S       = (const float*)d_in[3];   // (2048,)
    const float* Vt_real = (const float*)d_in[4];   // (2048, 1024)
    const float* Vt_imag = (const float*)d_in[5];   // (2048, 1024)
    const float* bias    = (const float*)d_in[6];   // (4096,)
    float* out           = (float*)d_out;           // (1024, 4096)

    float* scratch = nullptr;
    cudaGetSymbolAddress((void**)&scratch, g_scratch);
    float* B1 = scratch + OFF_B1;     // (2048, 4096)
    float* G  = scratch + OFF_G;      // (1024, 2048)
    float* Y  = scratch + OFF_Y;      // (1024, 2048)
    float* T  = scratch + OFF_T;      // (1024, 2048)
    float* Z  = scratch + OFF_Z;      // (1024, 1024)
    float2* tab4096 = reinterpret_cast<float2*>(scratch + OFF_TAB4096);
    float2* tab2048 = reinterpret_cast<float2*>(scratch + OFF_TAB2048);

    constexpr int M = 1024;

    // 0) root-of-unity tables
    gen_tables_kernel<<<16, 256>>>(tab4096, tab2048);

    // 1) basis matrices
    fill_basis_kernel<<<dim3(4, 2048), 256>>>(B1, tab4096, 4096, 1024);
    fill_basis_kernel<<<dim3(2, 1024), 256>>>(G,  tab2048, 2048, 512);

    // 2) Y = x @ B1^T          (1024 x 2048, K = 4096)
    gemm_nt_kernel<128, 128, 16, 8, 8><<<dim3(2048 / 128, M / 128), 256>>>(
        x, 4096, B1, B1, 4096, 4096, Y, 2048, 4096, nullptr, nullptr);

    // 3) T = (Y @ [Vt_real|Vt_imag]^T) * S   (1024 x 2048, K = 2048, split 1024)
    gemm_nt_kernel<128, 128, 16, 8, 8><<<dim3(2048 / 128, M / 128), 256>>>(
        Y, 2048, Vt_real, Vt_imag, 1024, 1024, T, 2048, 2048, S, nullptr);

    // 4) Z = T @ G^T            (1024 x 1024, K = 2048)  — 64-wide N tiles for occupancy
    gemm_nt_kernel<128, 64, 16, 8, 4><<<dim3(1024 / 64, M / 128), 256>>>(
        T, 2048, G, G, 2048, 2048, Z, 1024, 2048, nullptr, nullptr);

    // 5) out = Z @ [U_real|U_imag]^T + bias  (1024 x 4096, K = 1024, split 512)
    gemm_nt_kernel<128, 128, 16, 8, 8><<<dim3(4096 / 128, M / 128), 256>>>(
        Z, 1024, U_real, U_imag, 512, 512, out, 4096, 1024, nullptr, bias);
}

// round 3
// speedup vs baseline: 2.3718x; 2.3718x over previous
#include <cuda_runtime.h>
#include <cuda_bf16.h>
#include <cstdint>
#include <cstddef>

// ============================================================================
// out = x @ (irfft(U)·S @ irfft(V)).T + bias  as 4 NT bf16 GEMMs (mma.sync).
// fp32 emulated via bf16 hi/lo 3-term trick folded into K: A'=[Ah|Al|Ah],
// B'=[Bh|Bh|Bl], C = A'@B'^T = Ah·Bh + Al·Bh + Ah·Bl  (fp32 accumulate).
// ============================================================================

static constexpr double PI_D = 3.141592653589793238462643383279502884;

// ---------------- device scratch -------------------------------------------
#define DEVARR(name, n) __device__ __align__(128) __nv_bfloat16 name[n]
DEVARR(g_Xp,  1024ull * 12288);   // A of G1
DEVARR(g_B1p, 2048ull * 12288);   // B of G1
DEVARR(g_VTp, 2048ull * 6144);    // B of G2
DEVARR(g_Gp,  1024ull * 6144);    // B of G3
DEVARR(g_Up,  4096ull * 3072);    // B of G4
DEVARR(g_Yp,  1024ull * 6144);    // A of G2 (G1 out)
DEVARR(g_Tp,  1024ull * 6144);    // A of G3 (G2 out)
DEVARR(g_Zp,  1024ull * 3072);    // A of G4 (G3 out)
__device__ __align__(16) float2 g_tab4096[4096];
__device__ __align__(16) float2 g_tab2048[2048];

// ---------------- small helpers ---------------------------------------------
__device__ __forceinline__ uint32_t s2u(const void* p) {
    uint32_t a;
    asm("{ .reg .u64 t; cvta.to.shared.u64 t, %1; cvt.u32.u64 %0, t; }"
        : "=r"(a) : "l"(p));
    return a;
}
__device__ __forceinline__ void cpa16(uint32_t dst, const void* src) {
    asm volatile("cp.async.cg.shared.global [%0], [%1], 16;"
                 :: "r"(dst), "l"(src) : "memory");
}
#define CP_COMMIT() asm volatile("cp.async.commit_group;" ::: "memory")
#define CP_WAIT1()  asm volatile("cp.async.wait_group 1;" ::: "memory")

// SW128 swizzle inside a 128-row x 128-byte tile
__device__ __forceinline__ uint32_t swz(uint32_t r, uint32_t cb) {
    return r * 128u + (cb ^ ((r & 7u) << 4));
}
__device__ __forceinline__ uint32_t pack_bf(__nv_bfloat16 a, __nv_bfloat16 b) {
    __nv_bfloat162 t = __halves2bfloat162(a, b);
    return *reinterpret_cast<uint32_t*>(&t);
}

// ---------------- prep kernels -----------------------------------------------
__global__ void gen_tables_kernel(float2* __restrict__ t4, float2* __restrict__ t2) {
    int t = blockIdx.x * blockDim.x + threadIdx.x;
    if (t < 4096) {
        double a = (2.0 * PI_D / 4096.0) * (double)t;
        t4[t] = make_float2((float)cos(a), (float)sin(a));
    }
    if (t < 2048) {
        double a = (2.0 * PI_D / 2048.0) * (double)t;
        t2[t] = make_float2((float)cos(a), (float)sin(a));
    }
}

// basis rows [0,ncoef): (k==0 ? 1/n : (2/n)cos(2pi jk/n))
// rows [ncoef,2ncoef): (k==0 ? 0 : -(2/n)sin(2pi jk/n))
// out: [2*ncoef][3n] bf16, segments (hi, hi, lo)
__global__ void fill_basis3_kernel(__nv_bfloat16* __restrict__ out,
                                   const float2* __restrict__ tab, int n, int ncoef) {
    int j = blockIdx.x * blockDim.x + threadIdx.x;
    int kp = blockIdx.y;
    if (j >= n) return;
    bool is_sin = (kp >= ncoef);
    int k = is_sin ? (kp - ncoef) : kp;
    float inv = 1.0f / (float)n;
    float v;
    if (k == 0) {
        v = is_sin ? 0.0f : inv;
    } else {
        float2 cs = tab[(j * k) & (n - 1)];
        v = is_sin ? (-2.0f * inv * cs.y) : (2.0f * inv * cs.x);
    }
    __nv_bfloat16 h = __float2bfloat16(v);
    __nv_bfloat16 l = __float2bfloat16(v - __bfloat162float(h));
    size_t base = (size_t)kp * (3 * n) + j;
    out[base] = h;
    out[base + n] = h;
    out[base + 2 * n] = l;
}

// split fp32 (two concatenated sources per row) into 3-segment bf16.
// lo_seg = 1 (A-type: h,l,h) or 2 (B-type: h,h,l)
__global__ void split3_kernel(const float* __restrict__ s0, int w0,
                              const float* __restrict__ s1, int w1,
                              __nv_bfloat16* __restrict__ out, int rows, int lo_seg) {
    int w = w0 + w1;
    size_t total = (size_t)rows * w;
    for (size_t i = (size_t)blockIdx.x * blockDim.x + threadIdx.x; i < total;
         i += (size_t)gridDim.x * blockDim.x) {
        int r = (int)(i / w);
        int c = (int)(i % w);
        float v = (c < w0) ? s0[(size_t)r * w0 + c] : s1[(size_t)r * w1 + (c - w0)];
        __nv_bfloat16 h = __float2bfloat16(v);
        __nv_bfloat16 l = __float2bfloat16(v - __bfloat162float(h));
        size_t base = (size_t)r * (3 * w) + c;
        out[base]           = (lo_seg == 0) ? l : h;
        out[base + w]       = (lo_seg == 1) ? l : h;
        out[base + 2 * w]   = (lo_seg == 2) ? l : h;
    }
}

// ---------------- HMMA GEMM ----------------------------------------------------
// C[M,N] = A[M,Kp] @ B[N,Kp]^T, bf16 in, fp32 accum.
// EPI=0: v = C*scale(col); write bf16 hi/lo 3-seg rows of width 3*Kout (h,l,h).
// EPI=1: write fp32 C + bias(col) with row stride ldc.
template <int EPI>
__global__ void __launch_bounds__(256)
hmma_gemm(const __nv_bfloat16* __restrict__ A,
          const __nv_bfloat16* __restrict__ B, int Kp,
          const float* __restrict__ sc,     // scale (EPI=0) or bias (EPI=1); may be null
          __nv_bfloat16* __restrict__ Cbf, int Kout,
          float* __restrict__ Cf, int ldc) {
    constexpr int TILE = 16384;           // 128 rows x 128B
    extern __shared__ char dyn[];
    __shared__ float sparam[128];

    const int tid = threadIdx.x;
    const int wid = tid >> 5;
    const int lane = tid & 31;
    const int i0 = blockIdx.y * 128;
    const int j0 = blockIdx.x * 128;
    const uint32_t sbase = s2u(dyn);

    for (int i = tid; i < 128; i += 256)
        sparam[i] = sc ? sc[j0 + i] : ((EPI == 0) ? 1.0f : 0.0f);

    const int nch = Kp >> 6;

    // per-lane ldmatrix offsets
    const int arow = lane & 15;
    const int acol = lane & 16;                       // bytes
    const int brow = (lane & 7) + ((lane & 16) >> 1);
    const int bcol = (lane & 8) << 1;                 // bytes

    const int m0 = (wid >> 2) * 64;
    const int n0 = (wid & 3) * 32;

    float acc[4][4][4];
#pragma unroll
    for (int a = 0; a < 4; a++)
#pragma unroll
        for (int b = 0; b < 4; b++)
#pragma unroll
            for (int c = 0; c < 4; c++) acc[a][b][c] = 0.0f;

    auto load_stage = [&](int c, int stg) {
        const uint32_t sb = sbase + (uint32_t)stg * (2 * TILE);
        const int k0 = c << 6;
        const __nv_bfloat16* gA = A + (size_t)i0 * Kp + k0;
        const __nv_bfloat16* gB = B + (size_t)j0 * Kp + k0;
#pragma unroll
        for (int it = 0; it < 4; it++) {
            int s = tid + it * 256;
            int r = s >> 3, cc = s & 7;
            cpa16(sb + swz(r, cc * 16), gA + (size_t)r * Kp + cc * 8);
        }
#pragma unroll
        for (int it = 0; it < 4; it++) {
            int s = tid + it * 256;
            int r = s >> 3, cc = s & 7;
            cpa16(sb + TILE + swz(r, cc * 16), gB + (size_t)r * Kp + cc * 8);
        }
    };

    load_stage(0, 0);
    CP_COMMIT();
    if (nch > 1) load_stage(1, 1);
    CP_COMMIT();

    for (int c = 0; c < nch; c++) {
        CP_WAIT1();
        __syncthreads();
        if (c + 2 < nch) load_stage(c + 2, (c + 2) % 3);
        CP_COMMIT();

        const uint32_t sa = sbase + (uint32_t)(c % 3) * (2 * TILE);
        const uint32_t sb = sa + TILE;
#pragma unroll
        for (int kk = 0; kk < 4; kk++) {
            uint32_t aF[4][4];
#pragma unroll
            for (int mi = 0; mi < 4; mi++) {
                uint32_t ad = sa + swz(m0 + mi * 16 + arow, kk * 32 + acol);
                asm volatile(
                    "ldmatrix.sync.aligned.m8n8.x4.shared.b16 {%0,%1,%2,%3}, [%4];"
                    : "=r"(aF[mi][0]), "=r"(aF[mi][1]), "=r"(aF[mi][2]), "=r"(aF[mi][3])
                    : "r"(ad));
            }
            uint32_t bF[2][4];
#pragma unroll
            for (int nb = 0; nb < 2; nb++) {
                uint32_t bd = sb + swz(n0 + nb * 16 + brow, kk * 32 + bcol);
                asm volatile(
                    "ldmatrix.sync.aligned.m8n8.x4.shared.b16 {%0,%1,%2,%3}, [%4];"
                    : "=r"(bF[nb][0]), "=r"(bF[nb][1]), "=r"(bF[nb][2]), "=r"(bF[nb][3])
                    : "r"(bd));
            }
#pragma unroll
            for (int mi = 0; mi < 4; mi++)
#pragma unroll
                for (int ni = 0; ni < 4; ni++) {
                    asm volatile(
                        "mma.sync.aligned.m16n8k16.row.col.f32.bf16.bf16.f32 "
                        "{%0,%1,%2,%3}, {%4,%5,%6,%7}, {%8,%9}, {%0,%1,%2,%3};"
                        : "+f"(acc[mi][ni][0]), "+f"(acc[mi][ni][1]),
                          "+f"(acc[mi][ni][2]), "+f"(acc[mi][ni][3])
                        : "r"(aF[mi][0]), "r"(aF[mi][1]), "r"(aF[mi][2]), "r"(aF[mi][3]),
                          "r"(bF[ni >> 1][(ni & 1) * 2]), "r"(bF[ni >> 1][(ni & 1) * 2 + 1]));
                }
        }
    }

    // ---- epilogue ----
    const int tg = lane >> 2;
    const int ti = lane & 3;
#pragma unroll
    for (int mi = 0; mi < 4; mi++) {
#pragma unroll
        for (int ni = 0; ni < 4; ni++) {
            const int cl = n0 + ni * 8 + 2 * ti;
            const int gj = j0 + cl;
            const float p0 = sparam[cl];
            const float p1 = sparam[cl + 1];
#pragma unroll
            for (int h = 0; h < 2; h++) {
                const int gi = i0 + m0 + mi * 16 + tg + h * 8;
                const float c0 = acc[mi][ni][2 * h];
                const float c1 = acc[mi][ni][2 * h + 1];
                if (EPI == 0) {
                    const float v0 = c0 * p0, v1 = c1 * p1;
                    __nv_bfloat16 h0 = __float2bfloat16(v0);
                    __nv_bfloat16 h1 = __float2bfloat16(v1);
                    __nv_bfloat16 l0 = __float2bfloat16(v0 - __bfloat162float(h0));
                    __nv_bfloat16 l1 = __float2bfloat16(v1 - __bfloat162float(h1));
                    const uint32_t hp = pack_bf(h0, h1);
                    const uint32_t lp = pack_bf(l0, l1);
                    size_t base = (size_t)gi * (3 * Kout) + gj;
                    *reinterpret_cast<uint32_t*>(Cbf + base) = hp;
                    *reinterpret_cast<uint32_t*>(Cbf + base + Kout) = lp;
                    *reinterpret_cast<uint32_t*>(Cbf + base + 2 * Kout) = hp;
                } else {
                    float2 v = make_float2(c0 + p0, c1 + p1);
                    *reinterpret_cast<float2*>(Cf + (size_t)gi * ldc + gj) = v;
                }
            }
        }
    }
}

// ---------------- launcher ------------------------------------------------------
extern "C" void kernel_launch(void* const* d_in, const int* in_sizes, int n_in,
                              void* d_out, int out_size) {
    const float* x       = (const float*)d_in[0];   // (1024, 4096)
    const float* U_real  = (const float*)d_in[1];   // (4096, 512)
    const float* U_imag  = (const float*)d_in[2];   // (4096, 512)
    const float* S       = (const float*)d_in[3];   // (2048,)
    const float* Vt_real = (const float*)d_in[4];   // (2048, 1024)
    const float* Vt_imag = (const float*)d_in[5];   // (2048, 1024)
    const float* bias    = (const float*)d_in[6];   // (4096,)
    float* out           = (float*)d_out;           // (1024, 4096)

    void *Xp, *B1p, *VTp, *Gp, *Up, *Yp, *Tp, *Zp, *t4, *t2;
    cudaGetSymbolAddress(&Xp, g_Xp);
    cudaGetSymbolAddress(&B1p, g_B1p);
    cudaGetSymbolAddress(&VTp, g_VTp);
    cudaGetSymbolAddress(&Gp, g_Gp);
    cudaGetSymbolAddress(&Up, g_Up);
    cudaGetSymbolAddress(&Yp, g_Yp);
    cudaGetSymbolAddress(&Tp, g_Tp);
    cudaGetSymbolAddress(&Zp, g_Zp);
    cudaGetSymbolAddress(&t4, g_tab4096);
    cudaGetSymbolAddress(&t2, g_tab2048);

    constexpr int SMEM = 3 * 2 * 16384;  // 98304
    cudaFuncSetAttribute(hmma_gemm<0>, cudaFuncAttributeMaxDynamicSharedMemorySize, SMEM);
    cudaFuncSetAttribute(hmma_gemm<1>, cudaFuncAttributeMaxDynamicSharedMemorySize, SMEM);

    // ---- prep ----
    gen_tables_kernel<<<16, 256>>>((float2*)t4, (float2*)t2);
    fill_basis3_kernel<<<dim3(16, 2048), 256>>>((__nv_bfloat16*)B1p, (const float2*)t4,
                                                4096, 1024);
    fill_basis3_kernel<<<dim3(8, 1024), 256>>>((__nv_bfloat16*)Gp, (const float2*)t2,
                                               2048, 512);
    split3_kernel<<<2048, 256>>>(x, 4096, nullptr, 0, (__nv_bfloat16*)Xp, 1024, 1);
    split3_kernel<<<2048, 256>>>(Vt_real, 1024, Vt_imag, 1024,
                                 (__nv_bfloat16*)VTp, 2048, 2);
    split3_kernel<<<2048, 256>>>(U_real, 512, U_imag, 512,
                                 (__nv_bfloat16*)Up, 4096, 2);

    // ---- GEMM chain ----
    // 1) Y = X @ B1^T   (1024 x 2048, Kp=12288)
    hmma_gemm<0><<<dim3(16, 8), 256, SMEM>>>(
        (const __nv_bfloat16*)Xp, (const __nv_bfloat16*)B1p, 12288,
        nullptr, (__nv_bfloat16*)Yp, 2048, nullptr, 0);
    // 2) T = (Y @ VT^T) * S   (1024 x 2048, Kp=6144)
    hmma_gemm<0><<<dim3(16, 8), 256, SMEM>>>(
        (const __nv_bfloat16*)Yp, (const __nv_bfloat16*)VTp, 6144,
        S, (__nv_bfloat16*)Tp, 2048, nullptr, 0);
    // 3) Z = T @ G^T   (1024 x 1024, Kp=6144)
    hmma_gemm<0><<<dim3(8, 8), 256, SMEM>>>(
        (const __nv_bfloat16*)Tp, (const __nv_bfloat16*)Gp, 6144,
        nullptr, (__nv_bfloat16*)Zp, 1024, nullptr, 0);
    // 4) out = Z @ U^T + bias   (1024 x 4096, Kp=3072)
    hmma_gemm<1><<<dim3(32, 8), 256, SMEM>>>(
        (const __nv_bfloat16*)Zp, (const __nv_bfloat16*)Up, 3072,
        bias, nullptr, 0, out, 4096);
}

// round 4
// speedup vs baseline: 3.6932x; 1.5571x over previous
#include <cuda_runtime.h>
#include <cuda_bf16.h>
#include <cstdint>
#include <cstddef>

// ============================================================================
// out = x @ (irfft(U)·S @ irfft(V)).T + bias
// G1 (row-DFT of x) split into even/odd half-K GEMMs; all GEMMs bf16 hi/lo
// 3-term emulated fp32 on mma.sync, with separate h/l tiles (no dup segment).
// ============================================================================

static constexpr double PI_D = 3.141592653589793238462643383279502884;

// ---------------- device scratch ---------------------------------------------
#define DEVARR(name, n) __device__ __align__(128) __nv_bfloat16 name[n]
// G1 folded operands (K = 2112)
DEVARR(g_Xeh, 1024ull * 2112); DEVARR(g_Xel, 1024ull * 2112);
DEVARR(g_Xoh, 1024ull * 2112); DEVARR(g_Xol, 1024ull * 2112);
DEVARR(g_Cch, 1024ull * 2112); DEVARR(g_Ccl, 1024ull * 2112);  // cos basis
DEVARR(g_Csh, 1024ull * 2112); DEVARR(g_Csl, 1024ull * 2112);  // sin basis
// G2/G3/G4 operands
DEVARR(g_VTh, 2048ull * 2048); DEVARR(g_VTl, 2048ull * 2048);  // S pre-folded
DEVARR(g_Gh,  1024ull * 2048); DEVARR(g_Gl,  1024ull * 2048);
DEVARR(g_Uh,  4096ull * 1024); DEVARR(g_Ul,  4096ull * 1024);
// intermediates
DEVARR(g_Yh, 1024ull * 2048);  DEVARR(g_Yl, 1024ull * 2048);
DEVARR(g_Th, 1024ull * 2048);  DEVARR(g_Tl, 1024ull * 2048);
DEVARR(g_Zh, 1024ull * 1024);  DEVARR(g_Zl, 1024ull * 1024);
__device__ __align__(16) float2 g_tab4096[4096];
__device__ __align__(16) float2 g_tab2048[2048];

// ---------------- helpers ------------------------------------------------------
__device__ __forceinline__ uint32_t s2u(const void* p) {
    uint32_t a;
    asm("{ .reg .u64 t; cvta.to.shared.u64 t, %1; cvt.u32.u64 %0, t; }"
        : "=r"(a) : "l"(p));
    return a;
}
__device__ __forceinline__ void cpa16(uint32_t dst, const void* src) {
    asm volatile("cp.async.cg.shared.global [%0], [%1], 16;"
                 :: "r"(dst), "l"(src) : "memory");
}
#define CP_COMMIT() asm volatile("cp.async.commit_group;" ::: "memory")
#define CP_WAIT2()  asm volatile("cp.async.wait_group 2;" ::: "memory")

__device__ __forceinline__ uint32_t swz(uint32_t r, uint32_t cb) {
    return r * 128u + (cb ^ ((r & 7u) << 4));
}
__device__ __forceinline__ uint32_t pack_bf(__nv_bfloat16 a, __nv_bfloat16 b) {
    __nv_bfloat162 t = __halves2bfloat162(a, b);
    return *reinterpret_cast<uint32_t*>(&t);
}
__device__ __forceinline__ void split_bf(float v, __nv_bfloat16& h, __nv_bfloat16& l) {
    h = __float2bfloat16(v);
    l = __float2bfloat16(v - __bfloat162float(h));
}

// ---------------- prep kernels --------------------------------------------------
__global__ void gen_tables_kernel(float2* __restrict__ t4, float2* __restrict__ t2) {
    int t = blockIdx.x * blockDim.x + threadIdx.x;
    if (t < 4096) {
        double a = (2.0 * PI_D / 4096.0) * (double)t;
        t4[t] = make_float2((float)cos(a), (float)sin(a));
    }
    if (t < 2048) {
        double a = (2.0 * PI_D / 2048.0) * (double)t;
        t2[t] = make_float2((float)cos(a), (float)sin(a));
    }
}

// z=0: Ccos [1024 x 2112]; z=1: Csin [1024 x 2112]; z=2: G [1024 x 2048]
__global__ void fill_all_kernel(__nv_bfloat16* __restrict__ Cch, __nv_bfloat16* __restrict__ Ccl,
                                __nv_bfloat16* __restrict__ Csh, __nv_bfloat16* __restrict__ Csl,
                                __nv_bfloat16* __restrict__ Gh,  __nv_bfloat16* __restrict__ Gl,
                                const float2* __restrict__ t4, const float2* __restrict__ t2) {
    int j = blockIdx.x * blockDim.x + threadIdx.x;
    int kp = blockIdx.y;
    int z = blockIdx.z;
    float v;
    if (z < 2) {
        if (kp >= 1024 || j >= 2112) return;
        int k = kp;
        float w = (k == 0) ? (1.0f / 4096.0f) : (2.0f / 4096.0f);
        if (j < 2048) {
            float2 cs = t4[((long long)j * k) & 4095];
            v = (z == 0) ? w * cs.x : -w * cs.y;
        } else if (j == 2048) {
            v = (z == 0) ? ((k & 1) ? -w : w) : 0.0f;
        } else {
            v = 0.0f;
        }
        __nv_bfloat16 h, l; split_bf(v, h, l);
        size_t off = (size_t)kp * 2112 + j;
        if (z == 0) { Cch[off] = h; Ccl[off] = l; }
        else        { Csh[off] = h; Csl[off] = l; }
    } else {
        if (kp >= 1024 || j >= 2048) return;
        bool is_sin = (kp >= 512);
        int k = is_sin ? (kp - 512) : kp;
        if (k == 0) {
            v = is_sin ? 0.0f : (1.0f / 2048.0f);
        } else {
            float2 cs = t2[((long long)j * k) & 2047];
            float w = 2.0f / 2048.0f;
            v = is_sin ? -w * cs.y : w * cs.x;
        }
        __nv_bfloat16 h, l; split_bf(v, h, l);
        size_t off = (size_t)kp * 2048 + j;
        Gh[off] = h; Gl[off] = l;
    }
}

// fold x rows: e[j]=x[j]+x[4096-j], o[j]=x[j]-x[4096-j]; Nyquist col at j=2048
__global__ void foldX_kernel(const float* __restrict__ x,
                             __nv_bfloat16* __restrict__ Xeh, __nv_bfloat16* __restrict__ Xel,
                             __nv_bfloat16* __restrict__ Xoh, __nv_bfloat16* __restrict__ Xol) {
    size_t total = 1024ull * 2112;
    for (size_t i = (size_t)blockIdx.x * blockDim.x + threadIdx.x; i < total;
         i += (size_t)gridDim.x * blockDim.x) {
        int r = (int)(i / 2112);
        int j = (int)(i % 2112);
        float e, o;
        if (j == 0) {
            e = x[(size_t)r * 4096]; o = 0.0f;
        } else if (j < 2048) {
            float a = x[(size_t)r * 4096 + j];
            float b = x[(size_t)r * 4096 + 4096 - j];
            e = a + b; o = a - b;
        } else if (j == 2048) {
            e = x[(size_t)r * 4096 + 2048]; o = 0.0f;
        } else {
            e = 0.0f; o = 0.0f;
        }
        __nv_bfloat16 h, l;
        split_bf(e, h, l); Xeh[i] = h; Xel[i] = l;
        split_bf(o, h, l); Xoh[i] = h; Xol[i] = l;
    }
}

// split fp32 (two concatenated sources per row, optional per-row scale) to h/l
__global__ void split2_kernel(const float* __restrict__ s0, int w0,
                              const float* __restrict__ s1, int w1,
                              const float* __restrict__ scale,
                              __nv_bfloat16* __restrict__ Oh,
                              __nv_bfloat16* __restrict__ Ol, int rows) {
    int w = w0 + w1;
    size_t total = (size_t)rows * w;
    for (size_t i = (size_t)blockIdx.x * blockDim.x + threadIdx.x; i < total;
         i += (size_t)gridDim.x * blockDim.x) {
        int r = (int)(i / w);
        int c = (int)(i % w);
        float v = (c < w0) ? s0[(size_t)r * w0 + c] : s1[(size_t)r * w1 + (c - w0)];
        if (scale) v *= scale[r];
        __nv_bfloat16 h, l; split_bf(v, h, l);
        Oh[i] = h; Ol[i] = l;
    }
}

// ---------------- HMMA GEMM -------------------------------------------------------
struct GP {
    const __nv_bfloat16 *Ah0, *Al0, *Bh0, *Bl0;
    const __nv_bfloat16 *Ah1, *Al1, *Bh1, *Bl1;
};

// C[M,N] = Ah@Bh^T + Al@Bh^T + Ah@Bl^T (fp32 accum).
// blocks with blockIdx.x >= nxHalf use operand set 1 (B row index rebased).
// EPI=0: write bf16 h/l (Ch, Cl); EPI=1: write fp32 + bias (Cf).
template <int BN, int EPI>
__global__ void __launch_bounds__(256)
hmma_gemm(GP gp, int nxHalf, int K,
          const float* __restrict__ bias,
          __nv_bfloat16* __restrict__ Ch, __nv_bfloat16* __restrict__ Cl,
          float* __restrict__ Cf, int ldc) {
    constexpr int ATILE = 16384;              // 128 x 128B
    constexpr int BTILE = BN * 128;
    constexpr uint32_t STAGE = 2 * ATILE + 2 * BTILE;
    constexpr int NW = BN / 32;               // warps along N
    constexpr int MW = 8 / NW;                // warps along M
    constexpr int WM = 128 / MW;
    constexpr int MF = WM / 16;               // 16-row A frags per warp

    extern __shared__ char dyn[];
    __shared__ float sparam[BN];

    const int tid = threadIdx.x;
    const int wid = tid >> 5;
    const int lane = tid & 31;
    const int half = (blockIdx.x >= nxHalf) ? 1 : 0;
    const int jb = blockIdx.x - half * nxHalf;     // B row block
    const int i0 = blockIdx.y * 128;
    const int j0g = blockIdx.x * BN;               // global output col
    const uint32_t sbase = s2u(dyn);

    const __nv_bfloat16* Ah = half ? gp.Ah1 : gp.Ah0;
    const __nv_bfloat16* Al = half ? gp.Al1 : gp.Al0;
    const __nv_bfloat16* Bh = half ? gp.Bh1 : gp.Bh0;
    const __nv_bfloat16* Bl = half ? gp.Bl1 : gp.Bl0;

    if (EPI == 1)
        for (int i = tid; i < BN; i += 256) sparam[i] = bias ? bias[j0g + i] : 0.0f;

    const int nch = K >> 6;

    const int arow = lane & 15;
    const int acol = lane & 16;
    const int brow = (lane & 7) + ((lane & 16) >> 1);
    const int bcol = (lane & 8) << 1;

    const int m0 = (wid / NW) * WM;
    const int n0 = (wid % NW) * 32;

    float acc[MF][4][4];
#pragma unroll
    for (int a = 0; a < MF; a++)
#pragma unroll
        for (int b = 0; b < 4; b++)
#pragma unroll
            for (int c = 0; c < 4; c++) acc[a][b][c] = 0.0f;

    auto load_stage = [&](int c, int stg) {
        const uint32_t sb = sbase + (uint32_t)stg * STAGE;
        const int k0 = c << 6;
        const __nv_bfloat16* gAh = Ah + (size_t)i0 * K + k0;
        const __nv_bfloat16* gAl = Al + (size_t)i0 * K + k0;
        const __nv_bfloat16* gBh = Bh + (size_t)jb * BN * K + k0;
        const __nv_bfloat16* gBl = Bl + (size_t)jb * BN * K + k0;
        // A tiles: 2 x 128 rows x 8 float4
        for (int s = tid; s < 2048; s += 256) {
            int t = s >> 10;
            int r = (s & 1023) >> 3, cc = s & 7;
            const __nv_bfloat16* src = (t ? gAl : gAh) + (size_t)r * K + cc * 8;
            cpa16(sb + (uint32_t)t * ATILE + swz(r, cc * 16), src);
        }
        // B tiles: 2 x BN rows x 8 float4
        for (int s = tid; s < 2 * BN * 8; s += 256) {
            int t = s / (BN * 8);
            int rr = s % (BN * 8);
            int r = rr >> 3, cc = rr & 7;
            const __nv_bfloat16* src = (t ? gBl : gBh) + (size_t)r * K + cc * 8;
            cpa16(sb + 2 * ATILE + (uint32_t)t * BTILE + swz(r, cc * 16), src);
        }
    };

    load_stage(0, 0); CP_COMMIT();
    load_stage(1, 1); CP_COMMIT();
    load_stage(2, 2); CP_COMMIT();

    for (int c = 0; c < nch; c++) {
        CP_WAIT2();
        __syncthreads();

        const uint32_t sb = sbase + (uint32_t)(c % 3) * STAGE;
        const uint32_t sAh = sb;
        const uint32_t sAl = sb + ATILE;
        const uint32_t sBh = sb + 2 * ATILE;
        const uint32_t sBl = sBh + BTILE;

#pragma unroll
        for (int kk = 0; kk < 4; kk++) {
            uint32_t aH[MF][4];
#pragma unroll
            for (int mi = 0; mi < MF; mi++) {
                uint32_t ad = sAh + swz(m0 + mi * 16 + arow, kk * 32 + acol);
                asm volatile(
                    "ldmatrix.sync.aligned.m8n8.x4.shared.b16 {%0,%1,%2,%3}, [%4];"
                    : "=r"(aH[mi][0]), "=r"(aH[mi][1]), "=r"(aH[mi][2]), "=r"(aH[mi][3])
                    : "r"(ad));
            }
            uint32_t bH[2][4];
#pragma unroll
            for (int nb = 0; nb < 2; nb++) {
                uint32_t bd = sBh + swz(n0 + nb * 16 + brow, kk * 32 + bcol);
                asm volatile(
                    "ldmatrix.sync.aligned.m8n8.x4.shared.b16 {%0,%1,%2,%3}, [%4];"
                    : "=r"(bH[nb][0]), "=r"(bH[nb][1]), "=r"(bH[nb][2]), "=r"(bH[nb][3])
                    : "r"(bd));
            }
#pragma unroll
            for (int mi = 0; mi < MF; mi++)
#pragma unroll
                for (int ni = 0; ni < 4; ni++)
                    asm volatile(
                        "mma.sync.aligned.m16n8k16.row.col.f32.bf16.bf16.f32 "
                        "{%0,%1,%2,%3}, {%4,%5,%6,%7}, {%8,%9}, {%0,%1,%2,%3};"
                        : "+f"(acc[mi][ni][0]), "+f"(acc[mi][ni][1]),
                          "+f"(acc[mi][ni][2]), "+f"(acc[mi][ni][3])
                        : "r"(aH[mi][0]), "r"(aH[mi][1]), "r"(aH[mi][2]), "r"(aH[mi][3]),
                          "r"(bH[ni >> 1][(ni & 1) * 2]), "r"(bH[ni >> 1][(ni & 1) * 2 + 1]));

            // Ah @ Bl
            uint32_t bL[2][4];
#pragma unroll
            for (int nb = 0; nb < 2; nb++) {
                uint32_t bd = sBl + swz(n0 + nb * 16 + brow, kk * 32 + bcol);
                asm volatile(
                    "ldmatrix.sync.aligned.m8n8.x4.shared.b16 {%0,%1,%2,%3}, [%4];"
                    : "=r"(bL[nb][0]), "=r"(bL[nb][1]), "=r"(bL[nb][2]), "=r"(bL[nb][3])
                    : "r"(bd));
            }
#pragma unroll
            for (int mi = 0; mi < MF; mi++)
#pragma unroll
                for (int ni = 0; ni < 4; ni++)
                    asm volatile(
                        "mma.sync.aligned.m16n8k16.row.col.f32.bf16.bf16.f32 "
                        "{%0,%1,%2,%3}, {%4,%5,%6,%7}, {%8,%9}, {%0,%1,%2,%3};"
                        : "+f"(acc[mi][ni][0]), "+f"(acc[mi][ni][1]),
                          "+f"(acc[mi][ni][2]), "+f"(acc[mi][ni][3])
                        : "r"(aH[mi][0]), "r"(aH[mi][1]), "r"(aH[mi][2]), "r"(aH[mi][3]),
                          "r"(bL[ni >> 1][(ni & 1) * 2]), "r"(bL[ni >> 1][(ni & 1) * 2 + 1]));

            // Al @ Bh
            uint32_t aL[MF][4];
#pragma unroll
            for (int mi = 0; mi < MF; mi++) {
                uint32_t ad = sAl + swz(m0 + mi * 16 + arow, kk * 32 + acol);
                asm volatile(
                    "ldmatrix.sync.aligned.m8n8.x4.shared.b16 {%0,%1,%2,%3}, [%4];"
                    : "=r"(aL[mi][0]), "=r"(aL[mi][1]), "=r"(aL[mi][2]), "=r"(aL[mi][3])
                    : "r"(ad));
            }
#pragma unroll
            for (int mi = 0; mi < MF; mi++)
#pragma unroll
                for (int ni = 0; ni < 4; ni++)
                    asm volatile(
                        "mma.sync.aligned.m16n8k16.row.col.f32.bf16.bf16.f32 "
                        "{%0,%1,%2,%3}, {%4,%5,%6,%7}, {%8,%9}, {%0,%1,%2,%3};"
                        : "+f"(acc[mi][ni][0]), "+f"(acc[mi][ni][1]),
                          "+f"(acc[mi][ni][2]), "+f"(acc[mi][ni][3])
                        : "r"(aL[mi][0]), "r"(aL[mi][1]), "r"(aL[mi][2]), "r"(aL[mi][3]),
                          "r"(bH[ni >> 1][(ni & 1) * 2]), "r"(bH[ni >> 1][(ni & 1) * 2 + 1]));
        }
        __syncthreads();
        if (c + 3 < nch) load_stage(c + 3, (c + 3) % 3);
        CP_COMMIT();
    }

    // ---- epilogue ----
    const int tg = lane >> 2;
    const int ti = lane & 3;
#pragma unroll
    for (int mi = 0; mi < MF; mi++) {
#pragma unroll
        for (int ni = 0; ni < 4; ni++) {
            const int cl = n0 + ni * 8 + 2 * ti;
            const int gj = j0g + cl;
#pragma unroll
            for (int h = 0; h < 2; h++) {
                const int gi = i0 + m0 + mi * 16 + tg + h * 8;
                const float c0 = acc[mi][ni][2 * h];
                const float c1 = acc[mi][ni][2 * h + 1];
                if (EPI == 0) {
                    __nv_bfloat16 h0, l0, h1, l1;
                    split_bf(c0, h0, l0);
                    split_bf(c1, h1, l1);
                    size_t base = (size_t)gi * ldc + gj;
                    *reinterpret_cast<uint32_t*>(Ch + base) = pack_bf(h0, h1);
                    *reinterpret_cast<uint32_t*>(Cl + base) = pack_bf(l0, l1);
                } else {
                    float2 v = make_float2(c0 + sparam[cl], c1 + sparam[cl + 1]);
                    *reinterpret_cast<float2*>(Cf + (size_t)gi * ldc + gj) = v;
                }
            }
        }
    }
}

// ---------------- launcher ---------------------------------------------------------
extern "C" void kernel_launch(void* const* d_in, const int* in_sizes, int n_in,
                              void* d_out, int out_size) {
    const float* x       = (const float*)d_in[0];   // (1024, 4096)
    const float* U_real  = (const float*)d_in[1];   // (4096, 512)
    const float* U_imag  = (const float*)d_in[2];   // (4096, 512)
    const float* S       = (const float*)d_in[3];   // (2048,)
    const float* Vt_real = (const float*)d_in[4];   // (2048, 1024)
    const float* Vt_imag = (const float*)d_in[5];   // (2048, 1024)
    const float* bias    = (const float*)d_in[6];   // (4096,)
    float* out           = (float*)d_out;           // (1024, 4096)

#define GA(v, s) void* v; cudaGetSymbolAddress(&v, s)
    GA(Xeh, g_Xeh); GA(Xel, g_Xel); GA(Xoh, g_Xoh); GA(Xol, g_Xol);
    GA(Cch, g_Cch); GA(Ccl, g_Ccl); GA(Csh, g_Csh); GA(Csl, g_Csl);
    GA(VTh, g_VTh); GA(VTl, g_VTl); GA(Gh, g_Gh);   GA(Gl, g_Gl);
    GA(Uh, g_Uh);   GA(Ul, g_Ul);
    GA(Yh, g_Yh);   GA(Yl, g_Yl);   GA(Th, g_Th);   GA(Tl, g_Tl);
    GA(Zh, g_Zh);   GA(Zl, g_Zl);
    GA(t4, g_tab4096); GA(t2, g_tab2048);
#undef GA

    constexpr int SM128 = 3 * (2 * 16384 + 2 * 128 * 128);  // 196608
    constexpr int SM64  = 3 * (2 * 16384 + 2 * 64 * 128);   // 147456
    cudaFuncSetAttribute(hmma_gemm<128, 0>, cudaFuncAttributeMaxDynamicSharedMemorySize, SM128);
    cudaFuncSetAttribute(hmma_gemm<128, 1>, cudaFuncAttributeMaxDynamicSharedMemorySize, SM128);
    cudaFuncSetAttribute(hmma_gemm<64, 0>,  cudaFuncAttributeMaxDynamicSharedMemorySize, SM64);

    typedef const __nv_bfloat16* BP;

    // ---- prep (5 launches so G1 lands at ncu capture index 5) ----
    gen_tables_kernel<<<16, 256>>>((float2*)t4, (float2*)t2);
    fill_all_kernel<<<dim3(9, 1024, 3), 256>>>(
        (__nv_bfloat16*)Cch, (__nv_bfloat16*)Ccl, (__nv_bfloat16*)Csh, (__nv_bfloat16*)Csl,
        (__nv_bfloat16*)Gh, (__nv_bfloat16*)Gl, (const float2*)t4, (const float2*)t2);
    foldX_kernel<<<2048, 256>>>(x, (__nv_bfloat16*)Xeh, (__nv_bfloat16*)Xel,
                                (__nv_bfloat16*)Xoh, (__nv_bfloat16*)Xol);
    split2_kernel<<<2048, 256>>>(Vt_real, 1024, Vt_imag, 1024, S,
                                 (__nv_bfloat16*)VTh, (__nv_bfloat16*)VTl, 2048);
    split2_kernel<<<2048, 256>>>(U_real, 512, U_imag, 512, nullptr,
                                 (__nv_bfloat16*)Uh, (__nv_bfloat16*)Ul, 4096);

    // ---- GEMM chain ----
    // G1: Y[:,0:1024] = Xe @ Ccos^T, Y[:,1024:2048] = Xo @ Csin^T  (K=2112)
    {
        GP gp = {(BP)Xeh, (BP)Xel, (BP)Cch, (BP)Ccl,
                 (BP)Xoh, (BP)Xol, (BP)Csh, (BP)Csl};
        hmma_gemm<128, 0><<<dim3(16, 8), 256, SM128>>>(
            gp, 8, 2112, nullptr, (__nv_bfloat16*)Yh, (__nv_bfloat16*)Yl, nullptr, 2048);
    }
    // G2: T = Y @ (S·VT)^T   (1024 x 2048, K=2048)
    {
        GP gp = {(BP)Yh, (BP)Yl, (BP)VTh, (BP)VTl,
                 (BP)Yh, (BP)Yl, (BP)VTh, (BP)VTl};
        hmma_gemm<128, 0><<<dim3(16, 8), 256, SM128>>>(
            gp, 16, 2048, nullptr, (__nv_bfloat16*)Th, (__nv_bfloat16*)Tl, nullptr, 2048);
    }
    // G3: Z = T @ G^T   (1024 x 1024, K=2048), BN=64
    {
        GP gp = {(BP)Th, (BP)Tl, (BP)Gh, (BP)Gl,
                 (BP)Th, (BP)Tl, (BP)Gh, (BP)Gl};
        hmma_gemm<64, 0><<<dim3(16, 8), 256, SM64>>>(
            gp, 16, 2048, nullptr, (__nv_bfloat16*)Zh, (__nv_bfloat16*)Zl, nullptr, 1024);
    }
    // G4: out = Z @ U^T + bias   (1024 x 4096, K=1024)
    {
        GP gp = {(BP)Zh, (BP)Zl, (BP)Uh, (BP)Ul,
                 (BP)Zh, (BP)Zl, (BP)Uh, (BP)Ul};
        hmma_gemm<128, 1><<<dim3(32, 8), 256, SM128>>>(
            gp, 32, 1024, bias, nullptr, nullptr, out, 4096);
    }
}

// round 5
// speedup vs baseline: 4.6065x; 1.2473x over previous
#include <cuda_runtime.h>
#include <cuda_bf16.h>
#include <cstdint>
#include <cstddef>

// ============================================================================
// out = x @ (irfft(U)·S @ irfft(V)).T + bias
// G1 radix-4 folded (4 quarter GEMMs, K=1088), G3 radix-2 folded (2 half
// GEMMs, K=1088). All GEMMs bf16 hi/lo 3-term emulated fp32 on mma.sync.
// ============================================================================

static constexpr double PI_D = 3.141592653589793238462643383279502884;

// ---------------- device scratch ---------------------------------------------
// X quarters: [q][h/l][1024][1088]
__device__ __align__(128) __nv_bfloat16 g_XQ[4ull * 2 * 1024 * 1088];
// quarter bases (ce,co,se,so): [q][h/l][512][1088]
__device__ __align__(128) __nv_bfloat16 g_BQ[4ull * 2 * 512 * 1088];
// G half bases (cos,sin): [h2][h/l][512][1088]
__device__ __align__(128) __nv_bfloat16 g_GH[2ull * 2 * 512 * 1088];
// T folded: [cs][h/l][1024][1088]
__device__ __align__(128) __nv_bfloat16 g_TF[2ull * 2 * 1024 * 1088];
__device__ __align__(128) __nv_bfloat16 g_VTh[2048ull * 2048];
__device__ __align__(128) __nv_bfloat16 g_VTl[2048ull * 2048];
__device__ __align__(128) __nv_bfloat16 g_Uh[4096ull * 1024];
__device__ __align__(128) __nv_bfloat16 g_Ul[4096ull * 1024];
__device__ __align__(128) __nv_bfloat16 g_Yh[1024ull * 2048];
__device__ __align__(128) __nv_bfloat16 g_Yl[1024ull * 2048];
__device__ __align__(128) __nv_bfloat16 g_Zh[1024ull * 1024];
__device__ __align__(128) __nv_bfloat16 g_Zl[1024ull * 1024];
__device__ __align__(128) float g_T32[1024ull * 2048];
__device__ __align__(16) float2 g_tab4096[4096];
__device__ __align__(16) float2 g_tab2048[2048];

static constexpr int KQ = 1088;   // padded quarter/half K

// ---------------- helpers ------------------------------------------------------
__device__ __forceinline__ uint32_t s2u(const void* p) {
    uint32_t a;
    asm("{ .reg .u64 t; cvta.to.shared.u64 t, %1; cvt.u32.u64 %0, t; }"
        : "=r"(a) : "l"(p));
    return a;
}
__device__ __forceinline__ void cpa16(uint32_t dst, const void* src) {
    asm volatile("cp.async.cg.shared.global [%0], [%1], 16;"
                 :: "r"(dst), "l"(src) : "memory");
}
#define CP_COMMIT() asm volatile("cp.async.commit_group;" ::: "memory")
#define CP_WAIT2()  asm volatile("cp.async.wait_group 2;" ::: "memory")

__device__ __forceinline__ uint32_t swz(uint32_t r, uint32_t cb) {
    return r * 128u + (cb ^ ((r & 7u) << 4));
}
__device__ __forceinline__ uint32_t pack_bf(__nv_bfloat16 a, __nv_bfloat16 b) {
    __nv_bfloat162 t = __halves2bfloat162(a, b);
    return *reinterpret_cast<uint32_t*>(&t);
}
__device__ __forceinline__ void split_bf(float v, __nv_bfloat16& h, __nv_bfloat16& l) {
    h = __float2bfloat16(v);
    l = __float2bfloat16(v - __bfloat162float(h));
}

// pack 8 floats into hi/lo uint4s
__device__ __forceinline__ void pack8(const float* v, uint4& H, uint4& L) {
    __nv_bfloat16 h[8], l[8];
#pragma unroll
    for (int e = 0; e < 8; e++) split_bf(v[e], h[e], l[e]);
    H = *reinterpret_cast<uint4*>(h);
    L = *reinterpret_cast<uint4*>(l);
}

// ---------------- prep kernels --------------------------------------------------
__global__ void gen_tables_kernel(float2* __restrict__ t4, float2* __restrict__ t2) {
    int t = blockIdx.x * blockDim.x + threadIdx.x;
    if (t < 4096) {
        double a = (2.0 * PI_D / 4096.0) * (double)t;
        t4[t] = make_float2((float)cos(a), (float)sin(a));
    }
    if (t < 2048) {
        double a = (2.0 * PI_D / 2048.0) * (double)t;
        t2[t] = make_float2((float)cos(a), (float)sin(a));
    }
}

// z=0..3: quarter bases (ce, co, se, so) [512 x 1088]
// z=4..5: G half bases (cos, sin)        [512 x 1088]
__global__ void fill_bases_kernel(__nv_bfloat16* __restrict__ BQ,
                                  __nv_bfloat16* __restrict__ GH,
                                  const float2* __restrict__ t4,
                                  const float2* __restrict__ t2) {
    int jv = (blockIdx.x * blockDim.x + threadIdx.x) * 8;
    if (jv >= KQ) return;
    int kk = blockIdx.y;
    int z = blockIdx.z;
    float v[8];
#pragma unroll
    for (int e = 0; e < 8; e++) {
        int j = jv + e;
        float w = 0.0f;
        if (j <= 1024) {
            if (z < 4) {
                int k = 2 * kk + (z & 1);
                float ww = (k == 0) ? (1.0f / 4096.0f) : (2.0f / 4096.0f);
                float2 cs = t4[(j * k) & 4095];
                w = (z < 2) ? ww * cs.x : -ww * cs.y;
            } else {
                int k = kk;
                float ww = (k == 0) ? (1.0f / 2048.0f) : (2.0f / 2048.0f);
                float2 cs = t2[(j * k) & 2047];
                w = (z == 4) ? ww * cs.x : -ww * cs.y;
            }
        }
        v[e] = w;
    }
    uint4 H, L;
    pack8(v, H, L);
    __nv_bfloat16* base = (z < 4) ? BQ : GH;
    int zz = (z < 4) ? z : (z - 4);
    size_t offH = ((size_t)(zz * 2 + 0) * 512 + kk) * KQ + jv;
    size_t offL = ((size_t)(zz * 2 + 1) * 512 + kk) * KQ + jv;
    *reinterpret_cast<uint4*>(base + offH) = H;
    *reinterpret_cast<uint4*>(base + offL) = L;
}

// fold x rows into 4 quarter sequences (ee, eo, oe, oo) of width 1088
__global__ void foldX_kernel(const float* __restrict__ x,
                             __nv_bfloat16* __restrict__ XQ) {
    int t = blockIdx.x * blockDim.x + threadIdx.x;
    if (t >= 1024 * 136) return;
    int r = t / 136;
    int jv = (t % 136) * 8;
    const float* xr = x + (size_t)r * 4096;
    float vee[8], veo[8], voe[8], voo[8];
#pragma unroll
    for (int e = 0; e < 8; e++) {
        int j = jv + e;
        float ee = 0, eo = 0, oe = 0, oo = 0;
        if (j == 0) {
            float a = xr[0], n = xr[2048];
            ee = a + n; eo = a - n;
        } else if (j < 1024) {
            float a = xr[j], b = xr[4096 - j], c = xr[2048 - j], d = xr[2048 + j];
            float E = a + b, O = a - b, E2 = c + d, O2 = c - d;
            ee = E + E2; eo = E - E2; oe = O - O2; oo = O + O2;
        } else if (j == 1024) {
            float a = xr[1024], b = xr[3072];
            float E = a + b, O = a - b;
            ee = E; eo = E; oe = O; oo = O;
        }
        vee[e] = ee; veo[e] = eo; voe[e] = oe; voo[e] = oo;
    }
    uint4 H, L;
    size_t rb = (size_t)r * KQ + jv;
    size_t plane = 1024ull * KQ;
    pack8(vee, H, L);
    *reinterpret_cast<uint4*>(XQ + 0 * plane + rb) = H;
    *reinterpret_cast<uint4*>(XQ + 1 * plane + rb) = L;
    pack8(veo, H, L);
    *reinterpret_cast<uint4*>(XQ + 2 * plane + rb) = H;
    *reinterpret_cast<uint4*>(XQ + 3 * plane + rb) = L;
    pack8(voe, H, L);
    *reinterpret_cast<uint4*>(XQ + 4 * plane + rb) = H;
    *reinterpret_cast<uint4*>(XQ + 5 * plane + rb) = L;
    pack8(voo, H, L);
    *reinterpret_cast<uint4*>(XQ + 6 * plane + rb) = H;
    *reinterpret_cast<uint4*>(XQ + 7 * plane + rb) = L;
}

// VT split with column permutation matching folded-Y channel order, times S[l]
__global__ void splitVT_kernel(const float* __restrict__ Vt_real,
                               const float* __restrict__ Vt_imag,
                               const float* __restrict__ S,
                               __nv_bfloat16* __restrict__ Oh,
                               __nv_bfloat16* __restrict__ Ol) {
    int t = blockIdx.x * blockDim.x + threadIdx.x;
    if (t >= 2048 * 256) return;
    int l = t >> 8;
    int c0 = (t & 255) * 8;
    int q = c0 >> 9;
    const float* src = ((q < 2) ? Vt_real : Vt_imag) + (size_t)l * 1024;
    float s = S[l];
    float v[8];
#pragma unroll
    for (int e = 0; e < 8; e++) {
        int k = (((c0 & 511) + e) << 1) | (q & 1);
        v[e] = src[k] * s;
    }
    uint4 H, L;
    pack8(v, H, L);
    size_t off = (size_t)l * 2048 + c0;
    *reinterpret_cast<uint4*>(Oh + off) = H;
    *reinterpret_cast<uint4*>(Ol + off) = L;
}

__global__ void splitU_kernel(const float* __restrict__ U_real,
                              const float* __restrict__ U_imag,
                              __nv_bfloat16* __restrict__ Oh,
                              __nv_bfloat16* __restrict__ Ol) {
    int t = blockIdx.x * blockDim.x + threadIdx.x;
    if (t >= 4096 * 128) return;
    int r = t >> 7;
    int c0 = (t & 127) * 8;
    const float* src = ((c0 >> 9) ? U_imag : U_real) + (size_t)r * 512;
    float v[8];
#pragma unroll
    for (int e = 0; e < 8; e++) v[e] = src[(c0 & 511) + e];
    uint4 H, L;
    pack8(v, H, L);
    size_t off = (size_t)r * 1024 + c0;
    *reinterpret_cast<uint4*>(Oh + off) = H;
    *reinterpret_cast<uint4*>(Ol + off) = L;
}

// fold T (fp32, 1024x2048) into Tc/Ts h/l of width 1088
__global__ void foldT_kernel(const float* __restrict__ T,
                             __nv_bfloat16* __restrict__ TF) {
    int t = blockIdx.x * blockDim.x + threadIdx.x;
    if (t >= 1024 * 136) return;
    int r = t / 136;
    int jv = (t % 136) * 8;
    const float* Tr = T + (size_t)r * 2048;
    float vc[8], vs[8];
#pragma unroll
    for (int e = 0; e < 8; e++) {
        int j = jv + e;
        float c = 0, s = 0;
        if (j == 0) {
            c = Tr[0];
        } else if (j < 1024) {
            float a = Tr[j], b = Tr[2048 - j];
            c = a + b; s = a - b;
        } else if (j == 1024) {
            c = Tr[1024];
        }
        vc[e] = c; vs[e] = s;
    }
    uint4 H, L;
    size_t rb = (size_t)r * KQ + jv;
    size_t plane = 1024ull * KQ;
    pack8(vc, H, L);
    *reinterpret_cast<uint4*>(TF + 0 * plane + rb) = H;
    *reinterpret_cast<uint4*>(TF + 1 * plane + rb) = L;
    pack8(vs, H, L);
    *reinterpret_cast<uint4*>(TF + 2 * plane + rb) = H;
    *reinterpret_cast<uint4*>(TF + 3 * plane + rb) = L;
}

// ---------------- HMMA GEMM -------------------------------------------------------
struct GP4 {
    const __nv_bfloat16* Ah[4];
    const __nv_bfloat16* Al[4];
    const __nv_bfloat16* Bh[4];
    const __nv_bfloat16* Bl[4];
};

// C[M,N] = Ah@Bh^T + Al@Bh^T + Ah@Bl^T (fp32 accum), operand set =
// blockIdx.x / bpq, B row block = blockIdx.x % bpq.
// EPI=0: write bf16 h/l; EPI=1: write fp32 + bias(col).
template <int BN, int EPI>
__global__ void __launch_bounds__(256)
hmma_gemm(GP4 gp, int bpq, int K,
          const float* __restrict__ bias,
          __nv_bfloat16* __restrict__ Ch, __nv_bfloat16* __restrict__ Cl,
          float* __restrict__ Cf, int ldc) {
    constexpr int ATILE = 16384;
    constexpr int BTILE = BN * 128;
    constexpr uint32_t STAGE = 2 * ATILE + 2 * BTILE;
    constexpr int NW = BN / 32;
    constexpr int MW = 8 / NW;
    constexpr int WM = 128 / MW;
    constexpr int MF = WM / 16;

    extern __shared__ char dyn[];
    __shared__ float sparam[BN];

    const int tid = threadIdx.x;
    const int wid = tid >> 5;
    const int lane = tid & 31;
    const int setId = blockIdx.x / bpq;
    const int jb = blockIdx.x % bpq;
    const int i0 = blockIdx.y * 128;
    const int j0g = blockIdx.x * BN;
    const uint32_t sbase = s2u(dyn);

    const __nv_bfloat16* Ah = gp.Ah[setId];
    const __nv_bfloat16* Al = gp.Al[setId];
    const __nv_bfloat16* Bh = gp.Bh[setId];
    const __nv_bfloat16* Bl = gp.Bl[setId];

    if (EPI == 1)
        for (int i = tid; i < BN; i += 256) sparam[i] = bias ? bias[j0g + i] : 0.0f;

    const int nch = K >> 6;

    const int arow = lane & 15;
    const int acol = lane & 16;
    const int brow = (lane & 7) + ((lane & 16) >> 1);
    const int bcol = (lane & 8) << 1;

    const int m0 = (wid / NW) * WM;
    const int n0 = (wid % NW) * 32;

    float acc[MF][4][4];
#pragma unroll
    for (int a = 0; a < MF; a++)
#pragma unroll
        for (int b = 0; b < 4; b++)
#pragma unroll
            for (int c = 0; c < 4; c++) acc[a][b][c] = 0.0f;

    auto load_stage = [&](int c, int stg) {
        const uint32_t sb = sbase + (uint32_t)stg * STAGE;
        const int k0 = c << 6;
        const __nv_bfloat16* gAh = Ah + (size_t)i0 * K + k0;
        const __nv_bfloat16* gAl = Al + (size_t)i0 * K + k0;
        const __nv_bfloat16* gBh = Bh + (size_t)jb * BN * K + k0;
        const __nv_bfloat16* gBl = Bl + (size_t)jb * BN * K + k0;
        for (int s = tid; s < 2048; s += 256) {
            int t = s >> 10;
            int r = (s & 1023) >> 3, cc = s & 7;
            const __nv_bfloat16* src = (t ? gAl : gAh) + (size_t)r * K + cc * 8;
            cpa16(sb + (uint32_t)t * ATILE + swz(r, cc * 16), src);
        }
        for (int s = tid; s < 2 * BN * 8; s += 256) {
            int t = s / (BN * 8);
            int rr = s % (BN * 8);
            int r = rr >> 3, cc = rr & 7;
            const __nv_bfloat16* src = (t ? gBl : gBh) + (size_t)r * K + cc * 8;
            cpa16(sb + 2 * ATILE + (uint32_t)t * BTILE + swz(r, cc * 16), src);
        }
    };

    load_stage(0, 0); CP_COMMIT();
    load_stage(1, 1); CP_COMMIT();
    load_stage(2, 2); CP_COMMIT();

    for (int c = 0; c < nch; c++) {
        CP_WAIT2();
        __syncthreads();

        const uint32_t sb = sbase + (uint32_t)(c % 3) * STAGE;
        const uint32_t sAh = sb;
        const uint32_t sAl = sb + ATILE;
        const uint32_t sBh = sb + 2 * ATILE;
        const uint32_t sBl = sBh + BTILE;

#pragma unroll
        for (int kk = 0; kk < 4; kk++) {
            uint32_t aH[MF][4];
#pragma unroll
            for (int mi = 0; mi < MF; mi++) {
                uint32_t ad = sAh + swz(m0 + mi * 16 + arow, kk * 32 + acol);
                asm volatile(
                    "ldmatrix.sync.aligned.m8n8.x4.shared.b16 {%0,%1,%2,%3}, [%4];"
                    : "=r"(aH[mi][0]), "=r"(aH[mi][1]), "=r"(aH[mi][2]), "=r"(aH[mi][3])
                    : "r"(ad));
            }
            uint32_t bH[2][4];
#pragma unroll
            for (int nb = 0; nb < 2; nb++) {
                uint32_t bd = sBh + swz(n0 + nb * 16 + brow, kk * 32 + bcol);
                asm volatile(
                    "ldmatrix.sync.aligned.m8n8.x4.shared.b16 {%0,%1,%2,%3}, [%4];"
                    : "=r"(bH[nb][0]), "=r"(bH[nb][1]), "=r"(bH[nb][2]), "=r"(bH[nb][3])
                    : "r"(bd));
            }
#pragma unroll
            for (int mi = 0; mi < MF; mi++)
#pragma unroll
                for (int ni = 0; ni < 4; ni++)
                    asm volatile(
                        "mma.sync.aligned.m16n8k16.row.col.f32.bf16.bf16.f32 "
                        "{%0,%1,%2,%3}, {%4,%5,%6,%7}, {%8,%9}, {%0,%1,%2,%3};"
                        : "+f"(acc[mi][ni][0]), "+f"(acc[mi][ni][1]),
                          "+f"(acc[mi][ni][2]), "+f"(acc[mi][ni][3])
                        : "r"(aH[mi][0]), "r"(aH[mi][1]), "r"(aH[mi][2]), "r"(aH[mi][3]),
                          "r"(bH[ni >> 1][(ni & 1) * 2]), "r"(bH[ni >> 1][(ni & 1) * 2 + 1]));

            uint32_t bL[2][4];
#pragma unroll
            for (int nb = 0; nb < 2; nb++) {
                uint32_t bd = sBl + swz(n0 + nb * 16 + brow, kk * 32 + bcol);
                asm volatile(
                    "ldmatrix.sync.aligned.m8n8.x4.shared.b16 {%0,%1,%2,%3}, [%4];"
                    : "=r"(bL[nb][0]), "=r"(bL[nb][1]), "=r"(bL[nb][2]), "=r"(bL[nb][3])
                    : "r"(bd));
            }
#pragma unroll
            for (int mi = 0; mi < MF; mi++)
#pragma unroll
                for (int ni = 0; ni < 4; ni++)
                    asm volatile(
                        "mma.sync.aligned.m16n8k16.row.col.f32.bf16.bf16.f32 "
                        "{%0,%1,%2,%3}, {%4,%5,%6,%7}, {%8,%9}, {%0,%1,%2,%3};"
                        : "+f"(acc[mi][ni][0]), "+f"(acc[mi][ni][1]),
                          "+f"(acc[mi][ni][2]), "+f"(acc[mi][ni][3])
                        : "r"(aH[mi][0]), "r"(aH[mi][1]), "r"(aH[mi][2]), "r"(aH[mi][3]),
                          "r"(bL[ni >> 1][(ni & 1) * 2]), "r"(bL[ni >> 1][(ni & 1) * 2 + 1]));

            uint32_t aL[MF][4];
#pragma unroll
            for (int mi = 0; mi < MF; mi++) {
                uint32_t ad = sAl + swz(m0 + mi * 16 + arow, kk * 32 + acol);
                asm volatile(
                    "ldmatrix.sync.aligned.m8n8.x4.shared.b16 {%0,%1,%2,%3}, [%4];"
                    : "=r"(aL[mi][0]), "=r"(aL[mi][1]), "=r"(aL[mi][2]), "=r"(aL[mi][3])
                    : "r"(ad));
            }
#pragma unroll
            for (int mi = 0; mi < MF; mi++)
#pragma unroll
                for (int ni = 0; ni < 4; ni++)
                    asm volatile(
                        "mma.sync.aligned.m16n8k16.row.col.f32.bf16.bf16.f32 "
                        "{%0,%1,%2,%3}, {%4,%5,%6,%7}, {%8,%9}, {%0,%1,%2,%3};"
                        : "+f"(acc[mi][ni][0]), "+f"(acc[mi][ni][1]),
                          "+f"(acc[mi][ni][2]), "+f"(acc[mi][ni][3])
                        : "r"(aL[mi][0]), "r"(aL[mi][1]), "r"(aL[mi][2]), "r"(aL[mi][3]),
                          "r"(bH[ni >> 1][(ni & 1) * 2]), "r"(bH[ni >> 1][(ni & 1) * 2 + 1]));
        }
        __syncthreads();
        if (c + 3 < nch) load_stage(c + 3, (c + 3) % 3);
        CP_COMMIT();
    }

    const int tg = lane >> 2;
    const int ti = lane & 3;
#pragma unroll
    for (int mi = 0; mi < MF; mi++) {
#pragma unroll
        for (int ni = 0; ni < 4; ni++) {
            const int cl = n0 + ni * 8 + 2 * ti;
            const int gj = j0g + cl;
#pragma unroll
            for (int h = 0; h < 2; h++) {
                const int gi = i0 + m0 + mi * 16 + tg + h * 8;
                const float c0 = acc[mi][ni][2 * h];
                const float c1 = acc[mi][ni][2 * h + 1];
                if (EPI == 0) {
                    __nv_bfloat16 h0, l0, h1, l1;
                    split_bf(c0, h0, l0);
                    split_bf(c1, h1, l1);
                    size_t base = (size_t)gi * ldc + gj;
                    *reinterpret_cast<uint32_t*>(Ch + base) = pack_bf(h0, h1);
                    *reinterpret_cast<uint32_t*>(Cl + base) = pack_bf(l0, l1);
                } else {
                    float2 v = make_float2(c0 + sparam[cl], c1 + sparam[cl + 1]);
                    *reinterpret_cast<float2*>(Cf + (size_t)gi * ldc + gj) = v;
                }
            }
        }
    }
}

// ---------------- launcher ---------------------------------------------------------
extern "C" void kernel_launch(void* const* d_in, const int* in_sizes, int n_in,
                              void* d_out, int out_size) {
    const float* x       = (const float*)d_in[0];
    const float* U_real  = (const float*)d_in[1];
    const float* U_imag  = (const float*)d_in[2];
    const float* S       = (const float*)d_in[3];
    const float* Vt_real = (const float*)d_in[4];
    const float* Vt_imag = (const float*)d_in[5];
    const float* bias    = (const float*)d_in[6];
    float* out           = (float*)d_out;

#define GA(v, s) void* v; cudaGetSymbolAddress(&v, s)
    GA(XQ, g_XQ); GA(BQ, g_BQ); GA(GH, g_GH); GA(TF, g_TF);
    GA(VTh, g_VTh); GA(VTl, g_VTl); GA(Uh, g_Uh); GA(Ul, g_Ul);
    GA(Yh, g_Yh); GA(Yl, g_Yl); GA(Zh, g_Zh); GA(Zl, g_Zl);
    GA(T32, g_T32);
    GA(t4, g_tab4096); GA(t2, g_tab2048);
#undef GA

    constexpr int SM128 = 3 * (2 * 16384 + 2 * 128 * 128);  // 196608
    constexpr int SM64  = 3 * (2 * 16384 + 2 * 64 * 128);   // 147456
    cudaFuncSetAttribute(hmma_gemm<128, 0>, cudaFuncAttributeMaxDynamicSharedMemorySize, SM128);
    cudaFuncSetAttribute(hmma_gemm<128, 1>, cudaFuncAttributeMaxDynamicSharedMemorySize, SM128);
    cudaFuncSetAttribute(hmma_gemm<64, 0>,  cudaFuncAttributeMaxDynamicSharedMemorySize, SM64);

    typedef const __nv_bfloat16* BP;
    const size_t PX = 1024ull * KQ;   // X/T plane (h or l)
    const size_t PB = 512ull * KQ;    // basis plane

    // ---- prep ----
    gen_tables_kernel<<<16, 256>>>((float2*)t4, (float2*)t2);
    fill_bases_kernel<<<dim3(2, 512, 6), 128>>>((__nv_bfloat16*)BQ, (__nv_bfloat16*)GH,
                                                (const float2*)t4, (const float2*)t2);
    foldX_kernel<<<(1024 * 136 + 255) / 256, 256>>>(x, (__nv_bfloat16*)XQ);
    splitVT_kernel<<<2048, 256>>>(Vt_real, Vt_imag, S,
                                  (__nv_bfloat16*)VTh, (__nv_bfloat16*)VTl);
    splitU_kernel<<<2048, 256>>>(U_real, U_imag,
                                 (__nv_bfloat16*)Uh, (__nv_bfloat16*)Ul);

    // ---- G1: Y = 4 quarter GEMMs (1024 x 2048, K=1088) ----
    {
        GP4 gp;
        BP xq = (BP)XQ, bq = (BP)BQ;
        for (int q = 0; q < 4; q++) {
            gp.Ah[q] = xq + (2 * q + 0) * PX;
            gp.Al[q] = xq + (2 * q + 1) * PX;
            gp.Bh[q] = bq + (2 * q + 0) * PB;
            gp.Bl[q] = bq + (2 * q + 1) * PB;
        }
        hmma_gemm<128, 0><<<dim3(16, 8), 256, SM128>>>(
            gp, 4, KQ, nullptr, (__nv_bfloat16*)Yh, (__nv_bfloat16*)Yl, nullptr, 2048);
    }
    // ---- G2: T32 = Y @ (S*VTperm)^T  (1024 x 2048, K=2048), fp32 out ----
    {
        GP4 gp;
        for (int q = 0; q < 4; q++) {
            gp.Ah[q] = (BP)Yh; gp.Al[q] = (BP)Yl;
            gp.Bh[q] = (BP)VTh; gp.Bl[q] = (BP)VTl;
        }
        hmma_gemm<128, 1><<<dim3(16, 8), 256, SM128>>>(
            gp, 16, 2048, nullptr, nullptr, nullptr, (float*)T32, 2048);
    }
    // ---- fold T ----
    foldT_kernel<<<(1024 * 136 + 255) / 256, 256>>>((const float*)T32,
                                                    (__nv_bfloat16*)TF);
    // ---- G3: Z = 2 half GEMMs (1024 x 1024, K=1088) ----
    {
        GP4 gp;
        BP tf = (BP)TF, gh = (BP)GH;
        for (int q = 0; q < 4; q++) {
            int h2 = q & 1;          // sets 0..1 used (bpq=8, grid.x=16 -> set<2)
            gp.Ah[q] = tf + (2 * h2 + 0) * PX;
            gp.Al[q] = tf + (2 * h2 + 1) * PX;
            gp.Bh[q] = gh + (2 * h2 + 0) * PB;
            gp.Bl[q] = gh + (2 * h2 + 1) * PB;
        }
        // set = blockIdx.x / 8 (0 or 1): fix mapping so set matches h2
        GP4 gp2;
        for (int sidx = 0; sidx < 4; sidx++) {
            int h2 = (sidx < 1) ? 0 : 1;  // sets: 0 -> cos, 1 -> sin
            h2 = sidx;                     // direct: set index = half index
            if (h2 > 1) h2 = 1;
            gp2.Ah[sidx] = tf + (2 * h2 + 0) * PX;
            gp2.Al[sidx] = tf + (2 * h2 + 1) * PX;
            gp2.Bh[sidx] = gh + (2 * h2 + 0) * PB;
            gp2.Bl[sidx] = gh + (2 * h2 + 1) * PB;
        }
        hmma_gemm<64, 0><<<dim3(16, 8), 256, SM64>>>(
            gp2, 8, KQ, nullptr, (__nv_bfloat16*)Zh, (__nv_bfloat16*)Zl, nullptr, 1024);
    }
    // ---- G4: out = Z @ U^T + bias (1024 x 4096, K=1024) ----
    {
        GP4 gp;
        for (int q = 0; q < 4; q++) {
            gp.Ah[q] = (BP)Zh; gp.Al[q] = (BP)Zl;
            gp.Bh[q] = (BP)Uh; gp.Bl[q] = (BP)Ul;
        }
        hmma_gemm<128, 1><<<dim3(32, 8), 256, SM128>>>(
            gp, 32, 1024, bias, nullptr, nullptr, out, 4096);
    }
}